// round 9
// baseline (speedup 1.0000x reference)
#include <cuda_runtime.h>
#include <cstdint>

// CutOutput: per-row (8192 rows) stable descending argsort of D=1571 fp32,
// out[row][r] = (float)index_at_rank_r if r < len else 0, len = base[row].
// Output float32. Stability via packed-u64 (kk<<11)|idx tie-break.
//
// R9 (exposed-latency bound per R7/R8 evidence: no pipe saturated, duration
// insensitive to both occupancy and counted work): phase-2 ranking loop is a
// dependent LDS->CMP chain (29 cyc/iter serial). Batch bucket loads 4-wide
// so a typical bucket pays ONE shared-memory latency instead of 2-4.
// Padding slots use ~0ull (> any packed key) -> rank contribution 0.
// Len-aware pruning and singleton fast path retained from R8.

static constexpr int D = 1571;
static constexpr int NB = 2048;
static constexpr int THREADS = 512;
static constexpr int NE = 512;  // octave-table entries (e = kk>>23, 9 bits)

__device__ unsigned g_base[NE + 1];

__global__ void build_base_kernel() {
  const int t = threadIdx.x;
  if (t <= NE) {
    unsigned b;
    if (t == NE) {
      b = NB;
    } else {
      const unsigned kk0 = (unsigned)t << 23;  // lower edge of octave band t
      const unsigned a = ~kk0;
      const unsigned u = (a & 0x80000000u) ? (a ^ 0x80000000u) : ~a;
      const float x = __uint_as_float(u);      // band edge value (+/-inf ok)
      const float c = 0.5f * erfcf(x * 0.70710678118f);  // P(N(0,1) > x)
      b = (unsigned)(c * (float)NB);
      if (b > NB - 1u) b = NB - 1u;
    }
    g_base[t] = b;
  }
}

__global__ void __launch_bounds__(THREADS, 3) cutoutput_bucket_kernel(
    const float* __restrict__ to_cut,
    const int* __restrict__ candA,
    const int* __restrict__ candB,
    float* __restrict__ out) {
  __shared__ unsigned long long data[D];     // bucketed (kk<<11)|idx (live multi)
  __shared__ unsigned base[NE + 1];          // bucket-map table (copied)
  __shared__ unsigned startb[NB + 1];        // bucket start offsets
  __shared__ unsigned hist[NB];              // counts (preserved after scan)
  __shared__ unsigned wsum[16];              // scan partials
  __shared__ unsigned short staged[D];       // rank -> idx (only [0,len) used)

  const int t = threadIdx.x;
  const int row = blockIdx.x;
  const float* __restrict__ src = to_cut + (size_t)row * D;

  // base vs ids disambiguation: ids[0] == 0 always; base[0] >= 1 always.
  const int* __restrict__ basep = (candA[0] == 0) ? candB : candA;
  const unsigned len = (unsigned)basep[row];

  // ---- copy precomputed table; clear histogram ----
  if (t <= NE) base[t] = g_base[t];
#pragma unroll
  for (int k = 0; k < NB / THREADS; ++k) hist[t + k * THREADS] = 0;
  __syncthreads();

  // ---- phase 1: load, key, bucket, fused histogram+order ----
  unsigned kks[4];
  unsigned short bks[4];
  unsigned short ords[4];
#pragma unroll
  for (int k = 0; k < 4; ++k) {
    const int v = t + k * THREADS;
    if (v < D) {
      const unsigned u = __float_as_uint(src[v]);
      const unsigned a = u ^ ((u & 0x80000000u) ? 0xFFFFFFFFu : 0x80000000u);
      const unsigned kk = ~a;                     // ascending kk == desc value
      const unsigned e = kk >> 23;
      const unsigned b0 = base[e];
      const unsigned n = base[e + 1] - b0;
      const unsigned m = (kk >> 7) & 0xFFFFu;
      const unsigned bk = b0 + ((m * n) >> 16);   // exact monotone in kk
      kks[k] = kk;
      bks[k] = (unsigned short)bk;
      ords[k] = (unsigned short)atomicAdd(&hist[bk], 1u);  // arrival order
    }
  }
  __syncthreads();

  // ---- exclusive scan over NB=2048 buckets (4 per thread) ----
  {
    unsigned h[4];
    unsigned sum = 0;
#pragma unroll
    for (int k = 0; k < 4; ++k) {
      h[k] = hist[4 * t + k];
      sum += h[k];
    }
    unsigned v = sum;
#pragma unroll
    for (int d = 1; d < 32; d <<= 1) {
      unsigned nbr = __shfl_up_sync(0xFFFFFFFFu, v, d);
      if ((t & 31) >= d) v += nbr;
    }
    if ((t & 31) == 31) wsum[t >> 5] = v;
    __syncthreads();
    if (t < 16) {
      unsigned w = wsum[t];
#pragma unroll
      for (int d = 1; d < 16; d <<= 1) {
        unsigned nbr = __shfl_up_sync(0xFFFFu, w, d);
        if (t >= d) w += nbr;
      }
      wsum[t] = w;
    }
    __syncthreads();
    unsigned excl = v - sum + ((t >= 32) ? wsum[(t >> 5) - 1] : 0u);
#pragma unroll
    for (int k = 0; k < 4; ++k) {
      startb[4 * t + k] = excl;
      excl += h[k];
    }
    if (t == 0) startb[NB] = (unsigned)D;
  }
  __syncthreads();

  // ---- scatter: only LIVE buckets (startb < len); singleton fast path ----
#pragma unroll
  for (int k = 0; k < 4; ++k) {
    const int v = t + k * THREADS;
    if (v < D) {
      const unsigned bk = bks[k];
      const unsigned s = startb[bk];
      if (s >= len) {
        bks[k] = 0xFFFFu;                  // dead bucket: output is 0 anyway
      } else if (hist[bk] == 1u) {
        staged[s] = (unsigned short)v;     // rank known: bucket of one
        bks[k] = 0xFFFFu;
      } else {
        data[s + ords[k]] = ((unsigned long long)kks[k] << 11) | (unsigned)v;
      }
    }
  }
  __syncthreads();

  // ---- phase 2: per-element rank, 4-wide batched bucket loads (MLP) ----
#pragma unroll
  for (int k = 0; k < 4; ++k) {
    const int v = t + k * THREADS;
    if (v < D && bks[k] != 0xFFFFu) {
      const unsigned bk = bks[k];
      const unsigned s = startb[bk];
      const unsigned e = s + hist[bk];
      const unsigned long long ki =
          ((unsigned long long)kks[k] << 11) | (unsigned)v;
      unsigned r = s;
      for (unsigned j = s; j < e; j += 4) {
        // 4 independent LDS issued back-to-back: one latency, not four.
        const unsigned long long d0 = data[j];
        const unsigned long long d1 =
            (j + 1 < e) ? data[j + 1] : 0xFFFFFFFFFFFFFFFFull;
        const unsigned long long d2 =
            (j + 2 < e) ? data[j + 2] : 0xFFFFFFFFFFFFFFFFull;
        const unsigned long long d3 =
            (j + 3 < e) ? data[j + 3] : 0xFFFFFFFFFFFFFFFFull;
        r += (d0 < ki) ? 1u : 0u;
        r += (d1 < ki) ? 1u : 0u;
        r += (d2 < ki) ? 1u : 0u;
        r += (d3 < ki) ? 1u : 0u;
      }
      if (r < len) staged[r] = (unsigned short)v;
    }
  }
  __syncthreads();

  // ---- output: coalesced sweep with len mask ----
  float* __restrict__ dst = out + (size_t)row * D;
#pragma unroll
  for (int k = 0; k < 4; ++k) {
    const unsigned r = (unsigned)(t + k * THREADS);
    if (r < D) dst[r] = (r < len) ? (float)staged[r] : 0.0f;
  }
}

extern "C" void kernel_launch(void* const* d_in, const int* in_sizes, int n_in,
                              void* d_out, int out_size) {
  // to_cut is the (unique) large buffer: P*T*D elements.
  int imax = 0;
  for (int i = 1; i < n_in; ++i)
    if (in_sizes[i] > in_sizes[imax]) imax = i;
  const float* to_cut = (const float*)d_in[imax];

  int others[2], k = 0;
  for (int i = 0; i < n_in && k < 2; ++i)
    if (i != imax) others[k++] = i;
  const int* candA = (const int*)d_in[others[0]];
  const int* candB = (const int*)d_in[others[1]];

  float* out = (float*)d_out;
  const int rows = in_sizes[imax] / D;  // P*T = 8192

  build_base_kernel<<<1, NE + 32>>>();
  cutoutput_bucket_kernel<<<rows, THREADS>>>(to_cut, candA, candB, out);
}

// round 10
// speedup vs baseline: 1.0830x; 1.0830x over previous
#include <cuda_runtime.h>
#include <cstdint>

// CutOutput: per-row (8192 rows) stable descending argsort of D=1571 fp32,
// out[row][r] = (float)index_at_rank_r if r < len else 0, len = base[row].
// Output float32. Stability via packed-u64 (kk<<11)|idx tie-break.
//
// R10: ATOMS-wall theory. Four rounds pinned at ~97us across wildly varying
// occupancy/L1/work => smem atomic unit (~2 cyc/lane, per-SM serial) is the
// bottleneck: 1571 atomics/row * 2cyc * 55.4 blocks/SM ~= 98us. This round
// deletes ~35% of the atomics EXACTLY: elements with bucket >= T,
// T = (len+256)*NB/D+1, skip the histogram atomic. Scan stays valid (their
// counts are 0, startb monotone); we VERIFY startb[T] >= len post-scan
// (~10-sigma margin) and fall back to full counting + rescan if it ever
// fails. Skipped buckets then die in scatter via startb[bk] >= len.

static constexpr int D = 1571;
static constexpr int NB = 2048;
static constexpr int THREADS = 512;
static constexpr int NE = 512;  // octave-table entries (e = kk>>23, 9 bits)

__device__ unsigned g_base[NE + 1];

__global__ void build_base_kernel() {
  const int t = threadIdx.x;
  if (t <= NE) {
    unsigned b;
    if (t == NE) {
      b = NB;
    } else {
      const unsigned kk0 = (unsigned)t << 23;  // lower edge of octave band t
      const unsigned a = ~kk0;
      const unsigned u = (a & 0x80000000u) ? (a ^ 0x80000000u) : ~a;
      const float x = __uint_as_float(u);      // band edge value (+/-inf ok)
      const float c = 0.5f * erfcf(x * 0.70710678118f);  // P(N(0,1) > x)
      b = (unsigned)(c * (float)NB);
      if (b > NB - 1u) b = NB - 1u;
    }
    g_base[t] = b;
  }
}

__global__ void __launch_bounds__(THREADS) cutoutput_bucket_kernel(
    const float* __restrict__ to_cut,
    const int* __restrict__ candA,
    const int* __restrict__ candB,
    float* __restrict__ out) {
  __shared__ unsigned long long data[D];     // bucketed (kk<<11)|idx (live multi)
  __shared__ unsigned base[NE + 1];          // bucket-map table (copied)
  __shared__ unsigned startb[NB + 1];        // bucket start offsets
  __shared__ unsigned hist[NB];              // counts (preserved after scan)
  __shared__ unsigned wsum[16];              // scan partials
  __shared__ unsigned short staged[D];       // rank -> idx (only [0,len) used)

  const int t = threadIdx.x;
  const int row = blockIdx.x;
  const float* __restrict__ src = to_cut + (size_t)row * D;

  // base vs ids disambiguation: ids[0] == 0 always; base[0] >= 1 always.
  const int* __restrict__ basep = (candA[0] == 0) ? candB : candA;
  const unsigned len = (unsigned)basep[row];

  // Atomic-pruning threshold: buckets >= T almost surely start beyond len.
  unsigned T = (unsigned)(((unsigned long long)(len + 256u) * NB) / D + 1u);
  if (T > NB) T = NB;

  // ---- copy precomputed table; clear histogram ----
  if (t <= NE) base[t] = g_base[t];
#pragma unroll
  for (int k = 0; k < NB / THREADS; ++k) hist[t + k * THREADS] = 0;
  __syncthreads();

  // ---- phase 1: load, key, bucket; histogram atomic ONLY for bk < T ----
  unsigned kks[4];
  unsigned short bks[4];
  unsigned short ords[4];
#pragma unroll
  for (int k = 0; k < 4; ++k) {
    const int v = t + k * THREADS;
    if (v < D) {
      const unsigned u = __float_as_uint(src[v]);
      const unsigned a = u ^ ((u & 0x80000000u) ? 0xFFFFFFFFu : 0x80000000u);
      const unsigned kk = ~a;                     // ascending kk == desc value
      const unsigned e = kk >> 23;
      const unsigned b0 = base[e];
      const unsigned n = base[e + 1] - b0;
      const unsigned m = (kk >> 7) & 0xFFFFu;
      const unsigned bk = b0 + ((m * n) >> 16);   // exact monotone in kk
      kks[k] = kk;
      bks[k] = (unsigned short)bk;
      if (bk < T) {
        ords[k] = (unsigned short)atomicAdd(&hist[bk], 1u);  // arrival order
      } else {
        ords[k] = 0;  // unused unless fallback fills it
      }
    }
  }
  __syncthreads();

  // ---- scan (+ exact verification of the pruning; fallback if needed) ----
  for (int attempt = 0; attempt < 2; ++attempt) {
    {
      unsigned h[4];
      unsigned sum = 0;
#pragma unroll
      for (int k = 0; k < 4; ++k) {
        h[k] = hist[4 * t + k];
        sum += h[k];
      }
      unsigned v = sum;
#pragma unroll
      for (int d = 1; d < 32; d <<= 1) {
        unsigned nbr = __shfl_up_sync(0xFFFFFFFFu, v, d);
        if ((t & 31) >= d) v += nbr;
      }
      if ((t & 31) == 31) wsum[t >> 5] = v;
      __syncthreads();
      if (t < 16) {
        unsigned w = wsum[t];
#pragma unroll
        for (int d = 1; d < 16; d <<= 1) {
          unsigned nbr = __shfl_up_sync(0xFFFFu, w, d);
          if (t >= d) w += nbr;
        }
        wsum[t] = w;
      }
      __syncthreads();
      unsigned excl = v - sum + ((t >= 32) ? wsum[(t >> 5) - 1] : 0u);
#pragma unroll
      for (int k = 0; k < 4; ++k) {
        startb[4 * t + k] = excl;
        excl += h[k];
      }
      if (t == THREADS - 1) startb[NB] = excl;  // total counted
    }
    __syncthreads();

    if (T >= NB || startb[T] >= len) break;  // pruning proven exact

    // Fallback (prob ~0): count the skipped elements, rescan with T = NB.
#pragma unroll
    for (int k = 0; k < 4; ++k) {
      const int v = t + k * THREADS;
      if (v < D && bks[k] >= T) {
        ords[k] = (unsigned short)atomicAdd(&hist[bks[k]], 1u);
      }
    }
    T = NB;
    __syncthreads();
  }

  // ---- scatter: only LIVE buckets (startb < len); singleton fast path ----
  // Pruned buckets have startb[bk] >= startb[T] >= len -> auto-dead here.
#pragma unroll
  for (int k = 0; k < 4; ++k) {
    const int v = t + k * THREADS;
    if (v < D) {
      const unsigned bk = bks[k];
      const unsigned s = startb[bk];
      if (s >= len) {
        bks[k] = 0xFFFFu;                  // dead bucket: output is 0 anyway
      } else if (hist[bk] == 1u) {
        staged[s] = (unsigned short)v;     // rank known: bucket of one
        bks[k] = 0xFFFFu;
      } else {
        data[s + ords[k]] = ((unsigned long long)kks[k] << 11) | (unsigned)v;
      }
    }
  }
  __syncthreads();

  // ---- phase 2: per-element rank within live multi-element buckets ----
#pragma unroll
  for (int k = 0; k < 4; ++k) {
    const int v = t + k * THREADS;
    if (v < D && bks[k] != 0xFFFFu) {
      const unsigned bk = bks[k];
      const unsigned s = startb[bk];
      const unsigned e = s + hist[bk];
      const unsigned long long ki =
          ((unsigned long long)kks[k] << 11) | (unsigned)v;
      unsigned r = s;
      for (unsigned j = s; j < e; ++j) r += (data[j] < ki) ? 1u : 0u;
      if (r < len) staged[r] = (unsigned short)v;
    }
  }
  __syncthreads();

  // ---- output: coalesced sweep with len mask ----
  float* __restrict__ dst = out + (size_t)row * D;
#pragma unroll
  for (int k = 0; k < 4; ++k) {
    const unsigned r = (unsigned)(t + k * THREADS);
    if (r < D) dst[r] = (r < len) ? (float)staged[r] : 0.0f;
  }
}

extern "C" void kernel_launch(void* const* d_in, const int* in_sizes, int n_in,
                              void* d_out, int out_size) {
  // to_cut is the (unique) large buffer: P*T*D elements.
  int imax = 0;
  for (int i = 1; i < n_in; ++i)
    if (in_sizes[i] > in_sizes[imax]) imax = i;
  const float* to_cut = (const float*)d_in[imax];

  int others[2], k = 0;
  for (int i = 0; i < n_in && k < 2; ++i)
    if (i != imax) others[k++] = i;
  const int* candA = (const int*)d_in[others[0]];
  const int* candB = (const int*)d_in[others[1]];

  float* out = (float*)d_out;
  const int rows = in_sizes[imax] / D;  // P*T = 8192

  build_base_kernel<<<1, NE + 32>>>();
  cutoutput_bucket_kernel<<<rows, THREADS>>>(to_cut, candA, candB, out);
}

// round 11
// speedup vs baseline: 1.1587x; 1.0699x over previous
#include <cuda_runtime.h>
#include <cstdint>

// CutOutput: per-row (8192 rows) stable descending argsort of D=1571 fp32,
// out[row][r] = (float)index_at_rank_r if r < len else 0, len = base[row].
// Output float32. Stability via packed-u64 (kk<<11)|idx tie-break.
//
// R11 (issue-bound: issue=72%, ALU=51%, occ=95%): instruction diet.
//  * Packed octave table (b0 | n<<16): 1 LDS instead of 2 per element.
//  * uint4/float4 smem ops: hist clear, scan load/store, staged output read.
//  * staged[] holds float (convert once at producer, no I2F in output loop).
//  * Atomic-prune margin 256 -> 160 (~7 sigma; exact fallback retained).

static constexpr int D = 1571;
static constexpr int NB = 2048;
static constexpr int THREADS = 512;
static constexpr int NE = 512;  // octave-table entries (e = kk>>23, 9 bits)

__device__ unsigned g_pack[NE];  // per-octave: b0 | (span << 16)

__global__ void build_base_kernel() {
  const int t = threadIdx.x;
  if (t < NE) {
    // bucket-map edge for octave band t and t+1
    auto edge = [](unsigned tt) -> unsigned {
      if (tt >= NE) return NB;
      const unsigned kk0 = tt << 23;
      const unsigned a = ~kk0;
      const unsigned u = (a & 0x80000000u) ? (a ^ 0x80000000u) : ~a;
      const float x = __uint_as_float(u);
      const float c = 0.5f * erfcf(x * 0.70710678118f);  // P(N(0,1) > x)
      unsigned b = (unsigned)(c * (float)NB);
      return b > (NB - 1u) ? (NB - 1u) : b;
    };
    const unsigned b0 = edge(t);
    const unsigned b1 = edge(t + 1);
    g_pack[t] = b0 | ((b1 - b0) << 16);
  }
}

__global__ void __launch_bounds__(THREADS) cutoutput_bucket_kernel(
    const float* __restrict__ to_cut,
    const int* __restrict__ candA,
    const int* __restrict__ candB,
    float* __restrict__ out) {
  __shared__ unsigned long long data[D];        // bucketed (kk<<11)|idx
  __shared__ unsigned pbase[NE];                // packed octave table
  __shared__ alignas(16) unsigned startb[NB + 4];
  __shared__ alignas(16) unsigned hist[NB];
  __shared__ unsigned wsum[16];
  __shared__ alignas(16) float staged[D + 1];   // rank -> (float)idx

  const int t = threadIdx.x;
  const int row = blockIdx.x;
  const float* __restrict__ src = to_cut + (size_t)row * D;

  // base vs ids disambiguation: ids[0] == 0 always; base[0] >= 1 always.
  const int* __restrict__ basep = (candA[0] == 0) ? candB : candA;
  const unsigned len = (unsigned)basep[row];

  // Atomic-pruning threshold (~7 sigma margin; verified exactly below).
  unsigned T = (unsigned)(((unsigned long long)(len + 160u) * NB) / D + 1u);
  if (T > NB) T = NB;

  // ---- copy table; clear histogram (one STS.128) ----
  if (t < NE) pbase[t] = g_pack[t];
  reinterpret_cast<uint4*>(hist)[t] = make_uint4(0u, 0u, 0u, 0u);
  __syncthreads();

  // ---- phase 1: load, key, bucket; histogram atomic ONLY for bk < T ----
  unsigned kks[4];
  unsigned short bks[4];
  unsigned short ords[4];
#pragma unroll
  for (int k = 0; k < 4; ++k) {
    const int v = t + k * THREADS;
    if (v < D) {
      const unsigned u = __float_as_uint(src[v]);
      const unsigned a = u ^ ((u & 0x80000000u) ? 0xFFFFFFFFu : 0x80000000u);
      const unsigned kk = ~a;                     // ascending kk == desc value
      const unsigned pk = pbase[kk >> 23];
      const unsigned b0 = pk & 0xFFFFu;
      const unsigned n = pk >> 16;
      const unsigned m = (kk >> 7) & 0xFFFFu;
      const unsigned bk = b0 + ((m * n) >> 16);   // exact monotone in kk
      kks[k] = kk;
      bks[k] = (unsigned short)bk;
      ords[k] = (bk < T) ? (unsigned short)atomicAdd(&hist[bk], 1u)
                         : (unsigned short)0;
    }
  }
  __syncthreads();

  // ---- scan (vectorized) + exact verification of pruning ----
  for (int attempt = 0; attempt < 2; ++attempt) {
    {
      const uint4 h4 = reinterpret_cast<const uint4*>(hist)[t];
      const unsigned sum = h4.x + h4.y + h4.z + h4.w;
      unsigned v = sum;
#pragma unroll
      for (int d = 1; d < 32; d <<= 1) {
        unsigned nbr = __shfl_up_sync(0xFFFFFFFFu, v, d);
        if ((t & 31) >= d) v += nbr;
      }
      if ((t & 31) == 31) wsum[t >> 5] = v;
      __syncthreads();
      if (t < 16) {
        unsigned w = wsum[t];
#pragma unroll
        for (int d = 1; d < 16; d <<= 1) {
          unsigned nbr = __shfl_up_sync(0xFFFFu, w, d);
          if (t >= d) w += nbr;
        }
        wsum[t] = w;
      }
      __syncthreads();
      const unsigned excl = v - sum + ((t >= 32) ? wsum[(t >> 5) - 1] : 0u);
      reinterpret_cast<uint4*>(startb)[t] =
          make_uint4(excl, excl + h4.x, excl + h4.x + h4.y,
                     excl + h4.x + h4.y + h4.z);
      if (t == THREADS - 1) startb[NB] = excl + sum;
    }
    __syncthreads();

    if (T >= NB || startb[T] >= len) break;  // pruning proven exact

    // Fallback (prob ~0): count the skipped elements, rescan with T = NB.
#pragma unroll
    for (int k = 0; k < 4; ++k) {
      const int v = t + k * THREADS;
      if (v < D && bks[k] >= T) {
        ords[k] = (unsigned short)atomicAdd(&hist[bks[k]], 1u);
      }
    }
    T = NB;
    __syncthreads();
  }

  // ---- scatter: only LIVE buckets (startb < len); singleton fast path ----
#pragma unroll
  for (int k = 0; k < 4; ++k) {
    const int v = t + k * THREADS;
    if (v < D) {
      const unsigned bk = bks[k];
      const unsigned s = startb[bk];
      if (s >= len) {
        bks[k] = 0xFFFFu;                  // dead bucket: output is 0 anyway
      } else if (hist[bk] == 1u) {
        staged[s] = (float)v;              // rank known: bucket of one
        bks[k] = 0xFFFFu;
      } else {
        data[s + ords[k]] = ((unsigned long long)kks[k] << 11) | (unsigned)v;
      }
    }
  }
  __syncthreads();

  // ---- phase 2: per-element rank within live multi-element buckets ----
#pragma unroll
  for (int k = 0; k < 4; ++k) {
    const int v = t + k * THREADS;
    if (v < D && bks[k] != 0xFFFFu) {
      const unsigned bk = bks[k];
      const unsigned s = startb[bk];
      const unsigned e = s + hist[bk];
      const unsigned long long ki =
          ((unsigned long long)kks[k] << 11) | (unsigned)v;
      unsigned r = s;
      for (unsigned j = s; j < e; ++j) r += (data[j] < ki) ? 1u : 0u;
      if (r < len) staged[r] = (float)v;
    }
  }
  __syncthreads();

  // ---- output: float4 staged read, masked scalar stores (gmem row only
  //      4B-aligned: D*4 = 6284 bytes, so no STG.128) ----
  float* __restrict__ dst = out + (size_t)row * D;
  {
    const unsigned r0 = 4u * (unsigned)t;
    if (r0 < D) {
      const float4 sv = reinterpret_cast<const float4*>(staged)[t];
      const float o0 = (r0 < len) ? sv.x : 0.0f;
      const float o1 = (r0 + 1 < len) ? sv.y : 0.0f;
      const float o2 = (r0 + 2 < len) ? sv.z : 0.0f;
      const float o3 = (r0 + 3 < len) ? sv.w : 0.0f;
      dst[r0] = o0;
      if (r0 + 1 < D) dst[r0 + 1] = o1;
      if (r0 + 2 < D) dst[r0 + 2] = o2;
      if (r0 + 3 < D) dst[r0 + 3] = o3;
    }
  }
}

extern "C" void kernel_launch(void* const* d_in, const int* in_sizes, int n_in,
                              void* d_out, int out_size) {
  // to_cut is the (unique) large buffer: P*T*D elements.
  int imax = 0;
  for (int i = 1; i < n_in; ++i)
    if (in_sizes[i] > in_sizes[imax]) imax = i;
  const float* to_cut = (const float*)d_in[imax];

  int others[2], k = 0;
  for (int i = 0; i < n_in && k < 2; ++i)
    if (i != imax) others[k++] = i;
  const int* candA = (const int*)d_in[others[0]];
  const int* candB = (const int*)d_in[others[1]];

  float* out = (float*)d_out;
  const int rows = in_sizes[imax] / D;  // P*T = 8192

  build_base_kernel<<<1, NE>>>();
  cutoutput_bucket_kernel<<<rows, THREADS>>>(to_cut, candA, candB, out);
}